// round 2
// baseline (speedup 1.0000x reference)
#include <cuda_runtime.h>
#include <cuda_fp16.h>
#include <stdint.h>

// ---------------- problem constants ----------------
#define NQ_DIM   8
#define E_DIM    512
#define FFN_DIM  2048
#define TOKENS   32768           // B*S

// ---------------- tile config ----------------
#define M_TILE   128
#define N_TILE   256
#define KB       64
#define NKB      (FFN_DIM / KB)  // 32
#define THREADS  512             // 16 warps, 4x4 warp grid, warp tile 32x64

// ---------------- device scratch (no allocations allowed) ----------------
__device__ __half g_W2h[E_DIM * FFN_DIM];          // fp16 W2, [n=E][k=F], k contiguous
__device__ float2 g_w1p[NQ_DIM * (FFN_DIM / 2)];   // [q][f_pair] = (W1[2f][q], W1[2f+1][q])

// ---------------- smem layout ----------------
#define SM_MEAS  0               // 128*8*4   = 4 KB
#define SM_H0    4096            // 128*64*2  = 16 KB
#define SM_H1    20480
#define SM_W0    36864           // 256*64*2  = 32 KB
#define SM_W1    69632
#define SM_TOTAL 102400

#define SWZ(off) ((off) ^ (((off) >> 3) & 0x70))

// ---------------- PTX helpers ----------------
__device__ __forceinline__ uint32_t smem_u32(const void* p) {
    uint32_t a;
    asm("{ .reg .u64 t; cvta.to.shared.u64 t, %1; cvt.u32.u64 %0, t; }" : "=r"(a) : "l"(p));
    return a;
}

#define CP_ASYNC_16(dst, src) \
    asm volatile("cp.async.cg.shared.global [%0], [%1], 16;" :: "r"(dst), "l"(src) : "memory")
#define CP_ASYNC_COMMIT() asm volatile("cp.async.commit_group;" ::: "memory")
#define CP_ASYNC_WAIT0()  asm volatile("cp.async.wait_group 0;" ::: "memory")

#define PACK_F32X2(out, lo, hi) \
    asm("mov.b64 %0, {%1, %2};" : "=l"(out) : "r"(lo), "r"(hi))
#define UNPACK_F32X2(lo, hi, in) \
    asm("mov.b64 {%0, %1}, %2;" : "=r"(lo), "=r"(hi) : "l"(in))
#define FMA_F32X2(d, a, b, c) \
    asm("fma.rn.f32x2 %0, %1, %2, %3;" : "=l"(d) : "l"(a), "l"(b), "l"(c))

#define LDSM_X4(r0, r1, r2, r3, addr) \
    asm volatile("ldmatrix.sync.aligned.m8n8.x4.shared.b16 {%0,%1,%2,%3}, [%4];" \
                 : "=r"(r0), "=r"(r1), "=r"(r2), "=r"(r3) : "r"(addr))

#define MMA_16816(d, a, b) \
    asm volatile("mma.sync.aligned.m16n8k16.row.col.f32.f16.f16.f32 " \
                 "{%0,%1,%2,%3}, {%4,%5,%6,%7}, {%8,%9}, {%0,%1,%2,%3};" \
                 : "+f"((d)[0]), "+f"((d)[1]), "+f"((d)[2]), "+f"((d)[3]) \
                 : "r"((a)[0]), "r"((a)[1]), "r"((a)[2]), "r"((a)[3]), \
                   "r"((b)[0]), "r"((b)[1]))

// ---------------- prep: W2 -> fp16, W1 -> packed pairs ----------------
__global__ void ffq_prep(const float* __restrict__ W1, const float* __restrict__ W2) {
    int i = blockIdx.x * blockDim.x + threadIdx.x;
    if (i < E_DIM * FFN_DIM) g_W2h[i] = __float2half(W2[i]);
    if (i < NQ_DIM * (FFN_DIM / 2)) {
        int q  = i / (FFN_DIM / 2);
        int f2 = i % (FFN_DIM / 2);
        g_w1p[i] = make_float2(W1[(2 * f2) * NQ_DIM + q], W1[(2 * f2 + 1) * NQ_DIM + q]);
    }
}

// ---------------- W2 chunk prefetch (cp.async) ----------------
__device__ __forceinline__ void fetch_w2(uint32_t wbase, int kc, int n0, int tid) {
    #pragma unroll
    for (int j = 0; j < 4; j++) {
        int u = tid * 4 + j;             // 16B unit, 0..2047 (256 rows x 8 units)
        int r = u >> 3, g = u & 7;
        uint32_t off = (uint32_t)(r * 128 + g * 16);
        uint32_t dst = wbase + SWZ(off);
        const __half* src = g_W2h + (size_t)(n0 + r) * FFN_DIM + kc * KB + g * 8;
        CP_ASYNC_16(dst, (unsigned long long)__cvta_generic_to_global(src));
    }
    CP_ASYNC_COMMIT();
}

// ---------------- main fused kernel ----------------
__global__ void __launch_bounds__(THREADS, 1)
ffq_main(const float* __restrict__ x, const float* __restrict__ rxs, float* __restrict__ out) {
    extern __shared__ char smem[];
    const uint32_t sb = smem_u32(smem);
    const int tid = threadIdx.x;
    const int wid = tid >> 5;
    const int lid = tid & 31;
    const int token0 = blockIdx.x * M_TILE;
    const int n0     = blockIdx.y * N_TILE;

    const int wm = wid & 3;              // warp row: tokens [32*wm, +32)
    const int wn = wid >> 2;             // warp col: outs   [64*wn, +64)

    // prologue: start fetching W2 chunk 0 into stage 0
    fetch_w2(sb + SM_W0, 0, n0, tid);

    // meas[t][q] = cos(x[token0+t][q] + rxs[q])
    {
        float* meas = (float*)(smem + SM_MEAS);
        if (tid < 256) {
            int t = tid >> 1, h = tid & 1;
            float4 v = *(const float4*)(x + (size_t)(token0 + t) * E_DIM + h * 4);
            meas[t * 8 + h * 4 + 0] = cosf(v.x + rxs[h * 4 + 0]);
            meas[t * 8 + h * 4 + 1] = cosf(v.y + rxs[h * 4 + 1]);
            meas[t * 8 + h * 4 + 2] = cosf(v.z + rxs[h * 4 + 2]);
            meas[t * 8 + h * 4 + 3] = cosf(v.w + rxs[h * 4 + 3]);
        }
    }
    __syncthreads();

    // per-lane ldmatrix address components (SW128: swz(row*128+c) = row*128 + (c ^ (row&7)*16))
    const int arow  = 32 * wm + (lid & 7) + ((lid >> 3) & 1) * 8;  // A: m row (per mt add 16)
    const int acolh = (lid >> 4) * 16;                             // A: k-byte half
    const uint32_t amask = (uint32_t)((arow & 7) * 16);
    const int brow  = 64 * wn + (lid & 7) + (lid >> 4) * 8;        // B: n row (per bt add 16)
    const int bcolh = ((lid >> 3) & 1) * 16;                       // B: k-byte half
    const uint32_t bmask = (uint32_t)((lid & 7) * 16);

    float acc[2][8][4];
    #pragma unroll
    for (int mt = 0; mt < 2; mt++)
        #pragma unroll
        for (int nt = 0; nt < 8; nt++)
            #pragma unroll
            for (int c = 0; c < 4; c++) acc[mt][nt][c] = 0.0f;

    const float4* measv = (const float4*)(smem + SM_MEAS);
    const unsigned long long* w1pu = (const unsigned long long*)g_w1p;
    const int myt0 = wid * 8;            // h-compute: warp owns 8 tokens, lane = ffn pair

    for (int kc = 0; kc < NKB; kc++) {
        const int s = kc & 1;
        const uint32_t hs = sb + (s ? SM_H1 : SM_H0);
        const uint32_t ws = sb + (s ? SM_W1 : SM_W0);

        // ---- h chunk: 128 tokens x 64 ffn -> fp16x2, swizzled STS
        {
            unsigned long long w[8];
            #pragma unroll
            for (int q = 0; q < 8; q++)
                w[q] = w1pu[q * (FFN_DIM / 2) + kc * 32 + lid];

            #pragma unroll
            for (int i = 0; i < 8; i++) {
                const int t = myt0 + i;
                float4 m0 = measv[t * 2 + 0];
                float4 m1 = measv[t * 2 + 1];
                float mq[8] = {m0.x, m0.y, m0.z, m0.w, m1.x, m1.y, m1.z, m1.w};
                unsigned long long accp = 0ull;
                #pragma unroll
                for (int q = 0; q < 8; q++) {
                    unsigned long long mm;
                    uint32_t mu = __float_as_uint(mq[q]);
                    PACK_F32X2(mm, mu, mu);
                    FMA_F32X2(accp, mm, w[q], accp);
                }
                uint32_t alo, ahi;
                UNPACK_F32X2(alo, ahi, accp);
                float flo = fmaxf(__uint_as_float(alo), 0.0f);
                float fhi = fmaxf(__uint_as_float(ahi), 0.0f);
                uint32_t h2;
                asm("cvt.rn.f16x2.f32 %0, %1, %2;" : "=r"(h2) : "f"(fhi), "f"(flo));
                uint32_t off = (uint32_t)(t * 128 + lid * 4);
                asm volatile("st.shared.b32 [%0], %1;" :: "r"(hs + SWZ(off)), "r"(h2));
            }
        }

        CP_ASYNC_WAIT0();                // W2 chunk kc arrived
        __syncthreads();                 // h + W2 visible; all warps past mma(kc-1)

        if (kc + 1 < NKB)
            fetch_w2(sb + ((s ^ 1) ? SM_W1 : SM_W0), kc + 1, n0, tid);

        // ---- mma: warp tile 32x64, K=64 in 4 k16 steps
        #pragma unroll
        for (int ks = 0; ks < 4; ks++) {
            uint32_t a[2][4];
            #pragma unroll
            for (int mt = 0; mt < 2; mt++) {
                uint32_t addr = hs + (uint32_t)((arow + mt * 16) * 128)
                              + (((uint32_t)(ks * 32 + acolh)) ^ amask);
                LDSM_X4(a[mt][0], a[mt][1], a[mt][2], a[mt][3], addr);
            }
            uint32_t b[8][2];
            #pragma unroll
            for (int bt = 0; bt < 4; bt++) {
                uint32_t addr = ws + (uint32_t)((brow + bt * 16) * 128)
                              + (((uint32_t)(ks * 32 + bcolh)) ^ bmask);
                uint32_t r0, r1, r2, r3;
                LDSM_X4(r0, r1, r2, r3, addr);
                b[2 * bt][0] = r0; b[2 * bt][1] = r1;
                b[2 * bt + 1][0] = r2; b[2 * bt + 1][1] = r3;
            }
            #pragma unroll
            for (int mt = 0; mt < 2; mt++)
                #pragma unroll
                for (int nt = 0; nt < 8; nt++)
                    MMA_16816(acc[mt][nt], a[mt], b[nt]);
        }
    }

    // ---- epilogue: register accumulators -> out (float2 stores)
    {
        const int gid = lid >> 2, tig = lid & 3;
        #pragma unroll
        for (int mt = 0; mt < 2; mt++) {
            const int row = token0 + 32 * wm + mt * 16 + gid;
            #pragma unroll
            for (int nt = 0; nt < 8; nt++) {
                const int col = n0 + 64 * wn + nt * 8 + tig * 2;
                *(float2*)(out + (size_t)row * E_DIM + col) =
                    make_float2(acc[mt][nt][0], acc[mt][nt][1]);
                *(float2*)(out + (size_t)(row + 8) * E_DIM + col) =
                    make_float2(acc[mt][nt][2], acc[mt][nt][3]);
            }
        }
    }
}

// ---------------- launch ----------------
extern "C" void kernel_launch(void* const* d_in, const int* in_sizes, int n_in,
                              void* d_out, int out_size) {
    const float* x   = (const float*)d_in[0];   // [8,4096,512]
    const float* rxs = (const float*)d_in[1];   // [8]
    const float* W1  = (const float*)d_in[2];   // [2048,8]
    const float* W2  = (const float*)d_in[3];   // [512,2048]
    float* out = (float*)d_out;

    cudaFuncSetAttribute(ffq_main, cudaFuncAttributeMaxDynamicSharedMemorySize, SM_TOTAL);

    ffq_prep<<<(E_DIM * FFN_DIM + THREADS - 1) / THREADS, THREADS>>>(W1, W2);

    dim3 grid(TOKENS / M_TILE, E_DIM / N_TILE);  // (256, 2)
    ffq_main<<<grid, THREADS, SM_TOTAL>>>(x, rxs, out);
}